// round 8
// baseline (speedup 1.0000x reference)
#include <cuda_runtime.h>

#define B 512
#define T 512
#define H 128
#define G4 (4 * H)  // 512

// w1e stored as [b][h/4][t'][h%4]: hot loop does one LDG.128 per 4 h values
__device__ float g_w1eT4[(size_t)B * H * T];

#define K2LOG2E 2.885390082f  // 2*log2(e)

__device__ __forceinline__ float ex2f(float x) {
    float r;
    asm("ex2.approx.f32 %0, %1;" : "=f"(r) : "f"(x));
    return r;
}
__device__ __forceinline__ float rcpf(float x) {
    float r;
    asm("rcp.approx.f32 %0, %1;" : "=f"(r) : "f"(x));
    return r;
}
__device__ __forceinline__ float copysign_bits(float mag, float sgn) {
    unsigned int m = __float_as_uint(mag) & 0x7fffffffu;
    unsigned int s = __float_as_uint(sgn) & 0x80000000u;
    return __uint_as_float(m | s);
}

// ---- overflow-safe exp-based tanh: sign(x)*(1-E)/(1+E), E=e^{-2|x|} in (0,1] ----
__device__ __forceinline__ float tanh_safe(float x) {
    float y = x * K2LOG2E;          // 2x*log2e
    float m = fminf(y, -y);         // -|y|  (operand-neg is free in SASS)
    float E = ex2f(m);              // e^{-2|x|}, never overflows
    float den = E + 1.0f;
    float r = rcpf(den);
    r = r * fmaf(-den, r, 2.0f);    // Newton -> ~1 ulp
    float t = (1.0f - E) * r;       // tanh(|x|)
    return copysign_bits(t, x);
}
__device__ __forceinline__ float sigmoid_safe(float x) {
    return fmaf(0.5f, tanh_safe(0.5f * x), 0.5f);
}

// ---------------- w1eT4[b][h/4][t][h%4] = (enc @ W1) transposed+interleaved ----------------
__global__ void __launch_bounds__(256) w1e_kernel(const float* __restrict__ enc,
                                                  const float* __restrict__ W1) {
    extern __shared__ float smem[];
    float* sW1 = smem;               // 128*128
    float* senc = smem + 128 * 128;  // 64 * 129 padded
    int tid = threadIdx.x;
    int b = blockIdx.x >> 3;
    int t0 = (blockIdx.x & 7) * 64;

    for (int i = tid; i < 128 * 128; i += 256) sW1[i] = W1[i];
    for (int i = tid; i < 64 * 128; i += 256) {
        int r = i >> 7, k = i & 127;
        senc[r * 129 + k] = enc[((size_t)b * T + t0 + r) * H + k];
    }
    __syncthreads();

    int t = tid & 63, hg = tid >> 6;  // row t, h-group hg (32 h each)
    float acc[32];
#pragma unroll
    for (int i = 0; i < 32; i++) acc[i] = 0.0f;
#pragma unroll 4
    for (int k = 0; k < 128; k++) {
        float e = senc[t * 129 + k];
        const float4* w4 = (const float4*)(sW1 + k * 128 + hg * 32);
#pragma unroll
        for (int q = 0; q < 8; q++) {
            float4 w = w4[q];
            acc[q * 4 + 0] = fmaf(e, w.x, acc[q * 4 + 0]);
            acc[q * 4 + 1] = fmaf(e, w.y, acc[q * 4 + 1]);
            acc[q * 4 + 2] = fmaf(e, w.z, acc[q * 4 + 2]);
            acc[q * 4 + 3] = fmaf(e, w.w, acc[q * 4 + 3]);
        }
    }
    float4* gp = (float4*)g_w1eT4;
#pragma unroll
    for (int i4 = 0; i4 < 8; i4++) {
        float4 o = make_float4(acc[i4 * 4], acc[i4 * 4 + 1], acc[i4 * 4 + 2], acc[i4 * 4 + 3]);
        gp[((size_t)b * 32 + hg * 8 + i4) * T + t0 + t] = o;
    }
}

// ---------------- persistent per-batch decoder: 256 threads, 2 t' per thread ----------------
__global__ void __launch_bounds__(256) decoder_kernel(
    const float* __restrict__ x, const float* __restrict__ h0,
    const float* __restrict__ c0, const float* __restrict__ kern,
    const float* __restrict__ reck, const float* __restrict__ bias,
    const float* __restrict__ W2, const float* __restrict__ V,
    float* __restrict__ out) {
    __shared__ float sh[H];
    __shared__ float2 suv[H];  // {u*2log2e, V}
    __shared__ float sVs[H];
    __shared__ float sz[G4];
    __shared__ float sK0[G4], sK1[G4], sb[G4];
    __shared__ float sx[T * 2];
    __shared__ float sptr[2];
    __shared__ float rv[8];
    __shared__ int ri[8];

    int tid = threadIdx.x;
    int b = blockIdx.x;
    int lane = tid & 31, wid = tid >> 5;

    for (int i = tid; i < T * 2; i += 256) sx[i] = x[(size_t)b * T * 2 + i];
    for (int i = tid; i < G4; i += 256) {
        sK0[i] = kern[i];
        sK1[i] = kern[G4 + i];
        sb[i] = bias[i];
    }
    if (tid < H) { sh[tid] = h0[b * H + tid]; sVs[tid] = V[tid]; }
    float creg = (tid < H) ? c0[b * H + tid] : 0.0f;
    if (tid == 0) { sptr[0] = 1.0f; sptr[1] = 1.0f; }
    __syncthreads();

    const float4* wp4 = (const float4*)g_w1eT4 + (size_t)b * 32 * T;
    int r0 = tid, r1 = tid + 256;

    for (int s = 0; s < T; s++) {
        // ---- A: z = bias + ptr@K + h@R, 2 gate outputs per thread ----
        {
            float p0 = sptr[0], p1 = sptr[1];
            float z0 = fmaf(p1, sK1[r0], fmaf(p0, sK0[r0], sb[r0]));
            float z1 = fmaf(p1, sK1[r1], fmaf(p0, sK0[r1], sb[r1]));
            const float* rp = reck + r0;
#pragma unroll 8
            for (int h = 0; h < H; h++) {
                float hv = sh[h];
                z0 = fmaf(hv, __ldg(rp), z0);
                z1 = fmaf(hv, __ldg(rp + 256), z1);
                rp += G4;
            }
            sz[r0] = z0;
            sz[r1] = z1;
        }
        __syncthreads();

        // ---- B: gates (threads 0..127 own cell tid) ----
        if (tid < H) {
            float ig = sigmoid_safe(sz[tid]);
            float fg = sigmoid_safe(sz[tid + H]);
            float gg = tanh_safe(sz[tid + 2 * H]);
            float og = sigmoid_safe(sz[tid + 3 * H]);
            float c2 = fg * creg + ig * gg;
            creg = c2;
            sh[tid] = og * tanh_safe(c2);
        }
        __syncthreads();

        // ---- C: u = h2 @ W2; pack {u*2log2e, V} ----
        if (tid < H) {
            float u = 0.0f;
            const float* w2p = W2 + tid;
#pragma unroll 8
            for (int h = 0; h < H; h++) {
                u = fmaf(sh[h], __ldg(w2p), u);
                w2p += H;
            }
            suv[tid] = make_float2(u * K2LOG2E, sVs[tid]);
        }
        __syncthreads();

        // ---- D: score(t') = sum_h V[h] * tanh(w1e[h][t'] + u[h]) (safe form) ----
        float acc0 = 0.0f, acc1 = 0.0f;
#pragma unroll 4
        for (int q = 0; q < 32; q++) {
            float4 a0 = wp4[(size_t)q * T + r0];
            float4 a1 = wp4[(size_t)q * T + r1];
            float2 uv0 = suv[4 * q + 0];
            float2 uv1 = suv[4 * q + 1];
            float2 uv2 = suv[4 * q + 2];
            float2 uv3 = suv[4 * q + 3];
#define ELEM(av, uv, accv)                                         \
            {                                                      \
                float y = fmaf((av), K2LOG2E, (uv).x);             \
                float m = fminf(y, -y);                            \
                float E = ex2f(m);                                 \
                float den = E + 1.0f;                              \
                float r = rcpf(den);                               \
                r = r * fmaf(-den, r, 2.0f);                       \
                float t = (1.0f - E) * r;                          \
                t = copysign_bits(t, y);                           \
                (accv) = fmaf((uv).y, t, (accv));                  \
            }
            ELEM(a0.x, uv0, acc0) ELEM(a1.x, uv0, acc1)
            ELEM(a0.y, uv1, acc0) ELEM(a1.y, uv1, acc1)
            ELEM(a0.z, uv2, acc0) ELEM(a1.z, uv2, acc1)
            ELEM(a0.w, uv3, acc0) ELEM(a1.w, uv3, acc1)
#undef ELEM
        }
        size_t ob = ((size_t)b * T + s) * T;
        out[ob + r0] = acc0;
        out[ob + r1] = acc1;

        // ---- argmax (tie -> lowest index) + pointer select ----
        float best;
        int bidx;
        if (acc1 > acc0) { best = acc1; bidx = r1; }
        else             { best = acc0; bidx = r0; }
#pragma unroll
        for (int o = 16; o > 0; o >>= 1) {
            float ov = __shfl_xor_sync(0xffffffffu, best, o);
            int oi = __shfl_xor_sync(0xffffffffu, bidx, o);
            if (ov > best || (ov == best && oi < bidx)) { best = ov; bidx = oi; }
        }
        if (lane == 0) { rv[wid] = best; ri[wid] = bidx; }
        __syncthreads();
        if (wid == 0) {
            float bb = (lane < 8) ? rv[lane] : rv[0];
            int bi = (lane < 8) ? ri[lane] : ri[0];
#pragma unroll
            for (int o = 4; o > 0; o >>= 1) {
                float ov = __shfl_xor_sync(0xffffffffu, bb, o);
                int oi = __shfl_xor_sync(0xffffffffu, bi, o);
                if (ov > bb || (ov == bb && oi < bi)) { bb = ov; bi = oi; }
            }
            if (lane == 0) {
                sptr[0] = sx[bi * 2];
                sptr[1] = sx[bi * 2 + 1];
            }
        }
        __syncthreads();
    }
}

// ---------------- launch: 2 graph nodes ----------------
extern "C" void kernel_launch(void* const* d_in, const int* in_sizes, int n_in,
                              void* d_out, int out_size) {
    const float* x = (const float*)d_in[0];
    const float* enc = (const float*)d_in[1];
    const float* h0 = (const float*)d_in[2];
    const float* c0 = (const float*)d_in[3];
    const float* kern = (const float*)d_in[4];
    const float* reck = (const float*)d_in[5];
    const float* bias = (const float*)d_in[6];
    const float* W1 = (const float*)d_in[7];
    const float* W2 = (const float*)d_in[8];
    const float* V = (const float*)d_in[9];
    float* out = (float*)d_out;

    const int smem_w1e = (128 * 128 + 64 * 129) * 4;  // 98560 B
    cudaFuncSetAttribute(w1e_kernel, cudaFuncAttributeMaxDynamicSharedMemorySize, smem_w1e);
    w1e_kernel<<<B * 8, 256, smem_w1e>>>(enc, W1);
    decoder_kernel<<<B, 256>>>(x, h0, c0, kern, reck, bias, W2, V, out);
}

// round 9
// speedup vs baseline: 2.0780x; 2.0780x over previous
#include <cuda_runtime.h>

#define B 512
#define T 512
#define H 128
#define G4 (4 * H)  // 512

// w1e stored as [b][h/4][t'][h%4] float4s, PRE-SCALED by 2*log2(e)
__device__ float g_w1eT4[(size_t)B * H * T];

#define K2LOG2E 2.885390082f  // 2*log2(e)

__device__ __forceinline__ float ex2f(float x) {
    float r;
    asm("ex2.approx.f32 %0, %1;" : "=f"(r) : "f"(x));
    return r;
}
__device__ __forceinline__ float rcpf(float x) {
    float r;
    asm("rcp.approx.f32 %0, %1;" : "=f"(r) : "f"(x));
    return r;
}
__device__ __forceinline__ float copysign_bits(float mag, float sgn) {
    unsigned int m = __float_as_uint(mag) & 0x7fffffffu;
    unsigned int s = __float_as_uint(sgn) & 0x80000000u;
    return __uint_as_float(m | s);
}

// ---- gate tanh: negative-exponent safe form + Newton (accurate, NaN-proof) ----
__device__ __forceinline__ float tanh_safe(float x) {
    float y = x * K2LOG2E;
    float m = fminf(y, -y);         // -|y|
    float E = ex2f(m);              // e^{-2|x|} in (0,1]
    float den = E + 1.0f;
    float r = rcpf(den);
    r = r * fmaf(-den, r, 2.0f);    // Newton (den in [1,2], safe)
    float t = (1.0f - E) * r;
    return copysign_bits(t, x);
}
__device__ __forceinline__ float sigmoid_safe(float x) {
    return fmaf(0.5f, tanh_safe(0.5f * x), 0.5f);
}

// ---------------- w1eT4 = (enc @ W1) transposed+interleaved, prescaled ----------------
__global__ void __launch_bounds__(256) w1e_kernel(const float* __restrict__ enc,
                                                  const float* __restrict__ W1) {
    extern __shared__ float smem[];
    float* sW1 = smem;               // 128*128
    float* senc = smem + 128 * 128;  // 64 * 129 padded
    int tid = threadIdx.x;
    int b = blockIdx.x >> 3;
    int t0 = (blockIdx.x & 7) * 64;

    for (int i = tid; i < 128 * 128; i += 256) sW1[i] = W1[i];
    for (int i = tid; i < 64 * 128; i += 256) {
        int r = i >> 7, k = i & 127;
        senc[r * 129 + k] = enc[((size_t)b * T + t0 + r) * H + k];
    }
    __syncthreads();

    int t = tid & 63, hg = tid >> 6;
    float acc[32];
#pragma unroll
    for (int i = 0; i < 32; i++) acc[i] = 0.0f;
#pragma unroll 4
    for (int k = 0; k < 128; k++) {
        float e = senc[t * 129 + k];
        const float4* w4 = (const float4*)(sW1 + k * 128 + hg * 32);
#pragma unroll
        for (int q = 0; q < 8; q++) {
            float4 w = w4[q];
            acc[q * 4 + 0] = fmaf(e, w.x, acc[q * 4 + 0]);
            acc[q * 4 + 1] = fmaf(e, w.y, acc[q * 4 + 1]);
            acc[q * 4 + 2] = fmaf(e, w.z, acc[q * 4 + 2]);
            acc[q * 4 + 3] = fmaf(e, w.w, acc[q * 4 + 3]);
        }
    }
    float4* gp = (float4*)g_w1eT4;
#pragma unroll
    for (int i4 = 0; i4 < 8; i4++) {
        float4 o = make_float4(acc[i4 * 4] * K2LOG2E, acc[i4 * 4 + 1] * K2LOG2E,
                               acc[i4 * 4 + 2] * K2LOG2E, acc[i4 * 4 + 3] * K2LOG2E);
        gp[((size_t)b * 32 + hg * 8 + i4) * T + t0 + t] = o;
    }
}

// ---------------- persistent per-batch decoder: 512 threads, 1 t' per thread ----------------
__global__ void __launch_bounds__(512, 2) decoder_kernel(
    const float* __restrict__ x, const float* __restrict__ h0,
    const float* __restrict__ c0, const float* __restrict__ kern,
    const float* __restrict__ reck, const float* __restrict__ bias,
    const float* __restrict__ W2, const float* __restrict__ V,
    float* __restrict__ out) {
    __shared__ float sh[H];
    __shared__ float4 suv4[H / 2];   // interleaved {u*2log2e, -2V} pairs
    __shared__ float sVs[H];
    __shared__ float sz[G4];
    __shared__ float spart[512];     // phase-C partials
    __shared__ float sK0[G4], sK1[G4], sb[G4];
    __shared__ float sx[T * 2];
    __shared__ float sptr[2];
    __shared__ float s_sumV;
    __shared__ float rv[16];
    __shared__ int ri[16];

    int tid = threadIdx.x;
    int b = blockIdx.x;
    int lane = tid & 31, wid = tid >> 5;

    for (int i = tid; i < T * 2; i += 512) sx[i] = x[(size_t)b * T * 2 + i];
    if (tid < G4) {
        sK0[tid] = kern[tid];
        sK1[tid] = kern[G4 + tid];
        sb[tid] = bias[tid];
    }
    if (tid < H) { sh[tid] = h0[b * H + tid]; sVs[tid] = V[tid]; }
    float creg = (tid < H) ? c0[b * H + tid] : 0.0f;
    if (tid == 0) { sptr[0] = 1.0f; sptr[1] = 1.0f; }
    __syncthreads();
    if (tid == 0) {
        float sv = 0.0f;
        for (int h = 0; h < H; h++) sv += sVs[h];
        s_sumV = sv;
    }
    __syncthreads();
    float sumV = s_sumV;

    const float4* wp4 = (const float4*)g_w1eT4 + (size_t)b * 32 * T;

    for (int s = 0; s < T; s++) {
        // ---- A: z[tid] = bias + ptr@K + h@R (512 gate outputs, 1/thread) ----
        {
            float p0 = sptr[0], p1 = sptr[1];
            float z = fmaf(p1, sK1[tid], fmaf(p0, sK0[tid], sb[tid]));
            const float* rp = reck + tid;
#pragma unroll 8
            for (int h = 0; h < H; h++)
                z = fmaf(sh[h], __ldg(rp + (size_t)h * G4), z);
            sz[tid] = z;
        }
        __syncthreads();

        // ---- B: gates (threads 0..127 own cell tid) ----
        if (tid < H) {
            float ig = sigmoid_safe(sz[tid]);
            float fg = sigmoid_safe(sz[tid + H]);
            float gg = tanh_safe(sz[tid + 2 * H]);
            float og = sigmoid_safe(sz[tid + 3 * H]);
            float c2 = fg * creg + ig * gg;
            creg = c2;
            sh[tid] = og * tanh_safe(c2);
        }
        __syncthreads();

        // ---- C: u = h2 @ W2, parallel over 512 threads (4 partials per j) ----
        {
            int p = tid >> 7, j = tid & 127;
            float u = 0.0f;
            const float* w2p = W2 + (size_t)(p * 32) * H + j;
#pragma unroll 8
            for (int h = 0; h < 32; h++) {
                u = fmaf(sh[p * 32 + h], __ldg(w2p), u);
                w2p += H;
            }
            spart[tid] = u;
        }
        __syncthreads();
        if (tid < H) {
            float u = spart[tid] + spart[tid + 128] + spart[tid + 256] + spart[tid + 384];
            float* sf = (float*)suv4;
            sf[2 * tid] = u * K2LOG2E;
            sf[2 * tid + 1] = -2.0f * sVs[tid];
        }
        __syncthreads();

        // ---- D: score(t'=tid) = sumV + sum_h (-2V[h]) / (e^{2(w1e+u)} + 1) ----
        float acc0 = 0.0f, acc1 = 0.0f, acc2 = 0.0f, acc3 = 0.0f;
        {
            const float4* wp = wp4 + tid;
#pragma unroll 8
            for (int q = 0; q < 32; q++) {
                float4 a = __ldcs(wp + (size_t)q * T);
                float4 A4 = suv4[2 * q];       // (u0', v0, u1', v1)
                float4 B4 = suv4[2 * q + 1];   // (u2', v2, u3', v3)
                // inf-safe: E=inf -> r=0 -> term 0 (tanh=+1 contributes via sumV)
                float r0 = rcpf(ex2f(a.x + A4.x) + 1.0f);
                float r1 = rcpf(ex2f(a.y + A4.z) + 1.0f);
                float r2 = rcpf(ex2f(a.z + B4.x) + 1.0f);
                float r3 = rcpf(ex2f(a.w + B4.z) + 1.0f);
                acc0 = fmaf(A4.y, r0, acc0);
                acc1 = fmaf(A4.w, r1, acc1);
                acc2 = fmaf(B4.y, r2, acc2);
                acc3 = fmaf(B4.w, r3, acc3);
            }
        }
        float score = sumV + ((acc0 + acc1) + (acc2 + acc3));
        __stcs(out + ((size_t)b * T + s) * T + tid, score);

        // ---- argmax (tie -> lowest index) + pointer select ----
        float best = score;
        int bidx = tid;
#pragma unroll
        for (int o = 16; o > 0; o >>= 1) {
            float ov = __shfl_xor_sync(0xffffffffu, best, o);
            int oi = __shfl_xor_sync(0xffffffffu, bidx, o);
            if (ov > best || (ov == best && oi < bidx)) { best = ov; bidx = oi; }
        }
        if (lane == 0) { rv[wid] = best; ri[wid] = bidx; }
        __syncthreads();
        if (wid == 0) {
            float bb = (lane < 16) ? rv[lane] : rv[0];
            int bi = (lane < 16) ? ri[lane] : ri[0];
#pragma unroll
            for (int o = 8; o > 0; o >>= 1) {
                float ov = __shfl_xor_sync(0xffffffffu, bb, o);
                int oi = __shfl_xor_sync(0xffffffffu, bi, o);
                if (ov > bb || (ov == bb && oi < bi)) { bb = ov; bi = oi; }
            }
            if (lane == 0) {
                sptr[0] = sx[bi * 2];
                sptr[1] = sx[bi * 2 + 1];
            }
        }
        __syncthreads();
    }
}

// ---------------- launch: 2 graph nodes ----------------
extern "C" void kernel_launch(void* const* d_in, const int* in_sizes, int n_in,
                              void* d_out, int out_size) {
    const float* x = (const float*)d_in[0];
    const float* enc = (const float*)d_in[1];
    const float* h0 = (const float*)d_in[2];
    const float* c0 = (const float*)d_in[3];
    const float* kern = (const float*)d_in[4];
    const float* reck = (const float*)d_in[5];
    const float* bias = (const float*)d_in[6];
    const float* W1 = (const float*)d_in[7];
    const float* W2 = (const float*)d_in[8];
    const float* V = (const float*)d_in[9];
    float* out = (float*)d_out;

    const int smem_w1e = (128 * 128 + 64 * 129) * 4;  // 98560 B
    cudaFuncSetAttribute(w1e_kernel, cudaFuncAttributeMaxDynamicSharedMemorySize, smem_w1e);
    w1e_kernel<<<B * 8, 256, smem_w1e>>>(enc, W1);
    decoder_kernel<<<B, 512>>>(x, h0, c0, kern, reck, bias, W2, V, out);
}

// round 10
// speedup vs baseline: 2.8540x; 1.3734x over previous
#include <cuda_runtime.h>

#define B 512
#define T 512
#define H 128
#define G4 (4 * H)  // 512

// w1e stored as [b][h/4][t'][h%4] float4s, PRE-SCALED by 2*log2(e), clamped <= 15
__device__ float g_w1eT4[(size_t)B * H * T];

#define K2LOG2E 2.885390082f  // 2*log2(e)

__device__ __forceinline__ float ex2f(float x) {
    float r;
    asm("ex2.approx.f32 %0, %1;" : "=f"(r) : "f"(x));
    return r;
}
__device__ __forceinline__ float rcpf(float x) {
    float r;
    asm("rcp.approx.f32 %0, %1;" : "=f"(r) : "f"(x));
    return r;
}
__device__ __forceinline__ float copysign_bits(float mag, float sgn) {
    unsigned int m = __float_as_uint(mag) & 0x7fffffffu;
    unsigned int s = __float_as_uint(sgn) & 0x80000000u;
    return __uint_as_float(m | s);
}

// ---- gate tanh: negative-exponent safe form + Newton (accurate, NaN-proof) ----
__device__ __forceinline__ float tanh_safe(float x) {
    float y = x * K2LOG2E;
    float m = fminf(y, -y);         // -|y|
    float E = ex2f(m);              // e^{-2|x|} in (0,1]
    float den = E + 1.0f;
    float r = rcpf(den);
    r = r * fmaf(-den, r, 2.0f);    // Newton (den in [1,2], safe)
    float t = (1.0f - E) * r;
    return copysign_bits(t, x);
}
__device__ __forceinline__ float sigmoid_safe(float x) {
    return fmaf(0.5f, tanh_safe(0.5f * x), 0.5f);
}

// ---------------- w1eT4 = (enc @ W1), transposed+interleaved, prescaled+clamped ----------------
__global__ void __launch_bounds__(256) w1e_kernel(const float* __restrict__ enc,
                                                  const float* __restrict__ W1) {
    extern __shared__ float smem[];
    float* sW1 = smem;               // 128*128
    float* senc = smem + 128 * 128;  // 64 * 129 padded
    int tid = threadIdx.x;
    int b = blockIdx.x >> 3;
    int t0 = (blockIdx.x & 7) * 64;

    for (int i = tid; i < 128 * 128; i += 256) sW1[i] = W1[i];
    for (int i = tid; i < 64 * 128; i += 256) {
        int r = i >> 7, k = i & 127;
        senc[r * 129 + k] = enc[((size_t)b * T + t0 + r) * H + k];
    }
    __syncthreads();

    int t = tid & 63, hg = tid >> 6;
    float acc[32];
#pragma unroll
    for (int i = 0; i < 32; i++) acc[i] = 0.0f;
#pragma unroll 4
    for (int k = 0; k < 128; k++) {
        float e = senc[t * 129 + k];
        const float4* w4 = (const float4*)(sW1 + k * 128 + hg * 32);
#pragma unroll
        for (int q = 0; q < 8; q++) {
            float4 w = w4[q];
            acc[q * 4 + 0] = fmaf(e, w.x, acc[q * 4 + 0]);
            acc[q * 4 + 1] = fmaf(e, w.y, acc[q * 4 + 1]);
            acc[q * 4 + 2] = fmaf(e, w.z, acc[q * 4 + 2]);
            acc[q * 4 + 3] = fmaf(e, w.w, acc[q * 4 + 3]);
        }
    }
    float4* gp = (float4*)g_w1eT4;
#pragma unroll
    for (int i4 = 0; i4 < 8; i4++) {
        float4 o = make_float4(fminf(acc[i4 * 4] * K2LOG2E, 15.0f),
                               fminf(acc[i4 * 4 + 1] * K2LOG2E, 15.0f),
                               fminf(acc[i4 * 4 + 2] * K2LOG2E, 15.0f),
                               fminf(acc[i4 * 4 + 3] * K2LOG2E, 15.0f));
        gp[((size_t)b * 32 + hg * 8 + i4) * T + t0 + t] = o;
    }
}

// ---------------- persistent per-batch decoder: 512 threads, 1 t' per thread ----------------
__global__ void __launch_bounds__(512, 2) decoder_kernel(
    const float* __restrict__ x, const float* __restrict__ h0,
    const float* __restrict__ c0, const float* __restrict__ kern,
    const float* __restrict__ reck, const float* __restrict__ bias,
    const float* __restrict__ W2, const float* __restrict__ V,
    float* __restrict__ out) {
    __shared__ float sh[H];
    __shared__ float4 su4[32];      // u*2log2e quads (clamped <= 15)
    __shared__ float4 sv4[32];      // -2V quads
    __shared__ float sVs[H];
    __shared__ float4 spart4[512];  // phase A/C partials (8 KB, reused)
    __shared__ float sK0[G4], sK1[G4], sb[G4];
    __shared__ float sx[T * 2];
    __shared__ float sptr[2];
    __shared__ float s_sumV;
    __shared__ float rv[16];
    __shared__ int ri[16];

    int tid = threadIdx.x;
    int b = blockIdx.x;
    int lane = tid & 31, wid = tid >> 5;

    for (int i = tid; i < T * 2; i += 512) sx[i] = x[(size_t)b * T * 2 + i];
    sK0[tid] = kern[tid];
    sK1[tid] = kern[G4 + tid];
    sb[tid] = bias[tid];
    if (tid < H) { sh[tid] = h0[b * H + tid]; sVs[tid] = V[tid]; }
    float creg = (tid < H) ? c0[b * H + tid] : 0.0f;
    if (tid == 0) { sptr[0] = 1.0f; sptr[1] = 1.0f; }
    __syncthreads();
    if (tid < H) ((float*)sv4)[tid] = -2.0f * sVs[tid];
    if (tid == 0) {
        float sv = 0.0f;
        for (int h = 0; h < H; h++) sv += sVs[h];
        s_sumV = sv;
    }
    __syncthreads();
    float sumV = s_sumV;

    const float4* wp4 = (const float4*)g_w1eT4 + (size_t)b * 32 * T + tid;

    for (int s = 0; s < T; s++) {
        // ---- A: partial z, thread (p = h-quarter, q = gate quad): 32 x LDG.128 ----
        {
            int p = tid >> 7, q = tid & 127;
            const float4* rk = (const float4*)reck + q;  // reck[h][4q..4q+3]
            float4 a = make_float4(0.f, 0.f, 0.f, 0.f);
            int hb = p * 32;
#pragma unroll 8
            for (int h = 0; h < 32; h++) {
                float hv = sh[hb + h];
                float4 r4 = __ldg(rk + (size_t)(hb + h) * 128);
                a.x = fmaf(hv, r4.x, a.x);
                a.y = fmaf(hv, r4.y, a.y);
                a.z = fmaf(hv, r4.z, a.z);
                a.w = fmaf(hv, r4.w, a.w);
            }
            spart4[tid] = a;  // layout: [p][q] = p*128+q = tid
        }
        __syncthreads();

        // ---- B: reduce z + gates (threads 0..127 own cell tid) ----
        if (tid < H) {
            const float* sp = (const float*)spart4;
            float p0 = sptr[0], p1 = sptr[1];
#define GATEZ(c) (fmaf(p1, sK1[c], fmaf(p0, sK0[c], sb[c])) \
                  + ((sp[(c)] + sp[512 + (c)]) + (sp[1024 + (c)] + sp[1536 + (c)])))
            float zi = GATEZ(tid);
            float zf = GATEZ(tid + 128);
            float zg = GATEZ(tid + 256);
            float zo = GATEZ(tid + 384);
#undef GATEZ
            float ig = sigmoid_safe(zi);
            float fg = sigmoid_safe(zf);
            float gg = tanh_safe(zg);
            float og = sigmoid_safe(zo);
            float c2 = fg * creg + ig * gg;
            creg = c2;
            sh[tid] = og * tanh_safe(c2);
        }
        __syncthreads();

        // ---- C: partial u, thread (p2 = h-16th, g = out quad): 8 x LDG.128 ----
        {
            int p2 = tid >> 5, g = tid & 31;
            const float4* w2 = (const float4*)W2 + g;  // W2[h][4g..4g+3]
            float4 a = make_float4(0.f, 0.f, 0.f, 0.f);
            int hb = p2 * 8;
#pragma unroll
            for (int h = 0; h < 8; h++) {
                float hv = sh[hb + h];
                float4 w = __ldg(w2 + (size_t)(hb + h) * 32);
                a.x = fmaf(hv, w.x, a.x);
                a.y = fmaf(hv, w.y, a.y);
                a.z = fmaf(hv, w.z, a.z);
                a.w = fmaf(hv, w.w, a.w);
            }
            spart4[tid] = a;  // layout: [p2][g] = p2*32+g = tid
        }
        __syncthreads();

        // ---- C-reduce: u'[j] clamped & scaled (threads 0..127) ----
        if (tid < H) {
            const float* sp = (const float*)spart4;
            float u = 0.0f;
#pragma unroll
            for (int p2 = 0; p2 < 16; p2++) u += sp[p2 * 128 + tid];
            ((float*)su4)[tid] = fminf(u * K2LOG2E, 15.0f);
        }
        __syncthreads();

        // ---- D: score(t'=tid) = sumV + sum over quads of [combined 4-way rcp] ----
        float acc0 = 0.0f, acc1 = 0.0f;
#pragma unroll 8
        for (int qd = 0; qd < 32; qd++) {
            float4 a = __ldcg(wp4 + (size_t)qd * T);  // prescaled, clamped <= 15
            float4 U = su4[qd];                        // clamped <= 15 -> exps <= 30
            float4 Vv = sv4[qd];                       // -2V
            float d0 = ex2f(a.x + U.x) + 1.0f;
            float d1 = ex2f(a.y + U.y) + 1.0f;
            float d2 = ex2f(a.z + U.z) + 1.0f;
            float d3 = ex2f(a.w + U.w) + 1.0f;
            float d01 = d0 * d1, d23 = d2 * d3;
            float n01 = Vv.x * d1;
            n01 = fmaf(Vv.y, d0, n01);
            float n23 = Vv.z * d3;
            n23 = fmaf(Vv.w, d2, n23);
            float num = n01 * d23;
            num = fmaf(n23, d01, num);
            float r = rcpf(d01 * d23);
            if (qd & 1) acc1 = fmaf(num, r, acc1);
            else        acc0 = fmaf(num, r, acc0);
        }
        float score = sumV + (acc0 + acc1);
        __stcs(out + ((size_t)b * T + s) * T + tid, score);

        // ---- argmax (tie -> lowest index) + pointer select ----
        float best = score;
        int bidx = tid;
#pragma unroll
        for (int o = 16; o > 0; o >>= 1) {
            float ov = __shfl_xor_sync(0xffffffffu, best, o);
            int oi = __shfl_xor_sync(0xffffffffu, bidx, o);
            if (ov > best || (ov == best && oi < bidx)) { best = ov; bidx = oi; }
        }
        if (lane == 0) { rv[wid] = best; ri[wid] = bidx; }
        __syncthreads();
        if (wid == 0) {
            float bb = (lane < 16) ? rv[lane] : rv[0];
            int bi = (lane < 16) ? ri[lane] : ri[0];
#pragma unroll
            for (int o = 8; o > 0; o >>= 1) {
                float ov = __shfl_xor_sync(0xffffffffu, bb, o);
                int oi = __shfl_xor_sync(0xffffffffu, bi, o);
                if (ov > bb || (ov == bb && oi < bi)) { bb = ov; bi = oi; }
            }
            if (lane == 0) {
                sptr[0] = sx[bi * 2];
                sptr[1] = sx[bi * 2 + 1];
            }
        }
        __syncthreads();
    }
}

// ---------------- launch: 2 graph nodes ----------------
extern "C" void kernel_launch(void* const* d_in, const int* in_sizes, int n_in,
                              void* d_out, int out_size) {
    const float* x = (const float*)d_in[0];
    const float* enc = (const float*)d_in[1];
    const float* h0 = (const float*)d_in[2];
    const float* c0 = (const float*)d_in[3];
    const float* kern = (const float*)d_in[4];
    const float* reck = (const float*)d_in[5];
    const float* bias = (const float*)d_in[6];
    const float* W1 = (const float*)d_in[7];
    const float* W2 = (const float*)d_in[8];
    const float* V = (const float*)d_in[9];
    float* out = (float*)d_out;

    const int smem_w1e = (128 * 128 + 64 * 129) * 4;  // 98560 B
    cudaFuncSetAttribute(w1e_kernel, cudaFuncAttributeMaxDynamicSharedMemorySize, smem_w1e);
    w1e_kernel<<<B * 8, 256, smem_w1e>>>(enc, W1);
    decoder_kernel<<<B, 512>>>(x, h0, c0, kern, reck, bias, W2, V, out);
}

// round 11
// speedup vs baseline: 3.3853x; 1.1862x over previous
#include <cuda_runtime.h>

#define B 512
#define T 512
#define H 128
#define G4 (4 * H)  // 512

// g_P stores P = 2^{min(2*log2e*w1e, 15)}  as [b][h/4][t'][h%4] float4 quads
__device__ float g_P[(size_t)B * H * T];

#define K2LOG2E 2.885390082f  // 2*log2(e)

__device__ __forceinline__ float ex2f(float x) {
    float r;
    asm("ex2.approx.f32 %0, %1;" : "=f"(r) : "f"(x));
    return r;
}
__device__ __forceinline__ float rcpf(float x) {
    float r;
    asm("rcp.approx.f32 %0, %1;" : "=f"(r) : "f"(x));
    return r;
}
__device__ __forceinline__ float copysign_bits(float mag, float sgn) {
    unsigned int m = __float_as_uint(mag) & 0x7fffffffu;
    unsigned int s = __float_as_uint(sgn) & 0x80000000u;
    return __uint_as_float(m | s);
}

// ---- gate tanh: negative-exponent safe form + Newton (accurate, NaN-proof) ----
__device__ __forceinline__ float tanh_safe(float x) {
    float y = x * K2LOG2E;
    float m = fminf(y, -y);         // -|y|
    float E = ex2f(m);              // e^{-2|x|} in (0,1]
    float den = E + 1.0f;
    float r = rcpf(den);
    r = r * fmaf(-den, r, 2.0f);    // Newton (den in [1,2], safe)
    float t = (1.0f - E) * r;
    return copysign_bits(t, x);
}

// ---------------- P = 2^{clamp(2log2e * (enc @ W1), <=15)}, transposed+interleaved ----------------
__global__ void __launch_bounds__(256) w1e_kernel(const float* __restrict__ enc,
                                                  const float* __restrict__ W1) {
    extern __shared__ float smem[];
    float* sW1 = smem;               // 128*128
    float* senc = smem + 128 * 128;  // 64 * 129 padded
    int tid = threadIdx.x;
    int b = blockIdx.x >> 3;
    int t0 = (blockIdx.x & 7) * 64;

    for (int i = tid; i < 128 * 128; i += 256) sW1[i] = W1[i];
    for (int i = tid; i < 64 * 128; i += 256) {
        int r = i >> 7, k = i & 127;
        senc[r * 129 + k] = enc[((size_t)b * T + t0 + r) * H + k];
    }
    __syncthreads();

    int t = tid & 63, hg = tid >> 6;
    float acc[32];
#pragma unroll
    for (int i = 0; i < 32; i++) acc[i] = 0.0f;
#pragma unroll 4
    for (int k = 0; k < 128; k++) {
        float e = senc[t * 129 + k];
        const float4* w4 = (const float4*)(sW1 + k * 128 + hg * 32);
#pragma unroll
        for (int q = 0; q < 8; q++) {
            float4 w = w4[q];
            acc[q * 4 + 0] = fmaf(e, w.x, acc[q * 4 + 0]);
            acc[q * 4 + 1] = fmaf(e, w.y, acc[q * 4 + 1]);
            acc[q * 4 + 2] = fmaf(e, w.z, acc[q * 4 + 2]);
            acc[q * 4 + 3] = fmaf(e, w.w, acc[q * 4 + 3]);
        }
    }
    float4* gp = (float4*)g_P;
#pragma unroll
    for (int i4 = 0; i4 < 8; i4++) {
        float4 o = make_float4(ex2f(fminf(acc[i4 * 4] * K2LOG2E, 15.0f)),
                               ex2f(fminf(acc[i4 * 4 + 1] * K2LOG2E, 15.0f)),
                               ex2f(fminf(acc[i4 * 4 + 2] * K2LOG2E, 15.0f)),
                               ex2f(fminf(acc[i4 * 4 + 3] * K2LOG2E, 15.0f)));
        gp[((size_t)b * 32 + hg * 8 + i4) * T + t0 + t] = o;
    }
}

// ---------------- persistent per-batch decoder: 512 threads, 1 t' per thread ----------------
__global__ void __launch_bounds__(512, 2) decoder_kernel(
    const float* __restrict__ x, const float* __restrict__ h0,
    const float* __restrict__ c0, const float* __restrict__ kern,
    const float* __restrict__ reck, const float* __restrict__ bias,
    const float* __restrict__ W2, const float* __restrict__ V,
    float* __restrict__ out) {
    __shared__ float sh[H];
    __shared__ float4 sEu4[32];     // Eu = 2^{u'} quads
    __shared__ float4 sv4[32];      // -2V quads
    __shared__ float sVs[H];
    __shared__ float4 spart4[512];  // phase A/C partials (8 KB, reused)
    __shared__ float sact[G4];      // gate activations
    __shared__ float sK0[G4], sK1[G4], sb[G4];
    __shared__ float sx[T * 2];
    __shared__ float sptr[2];
    __shared__ float s_sumV;
    __shared__ float rv[16];
    __shared__ int ri[16];

    int tid = threadIdx.x;
    int b = blockIdx.x;
    int lane = tid & 31, wid = tid >> 5;

    for (int i = tid; i < T * 2; i += 512) sx[i] = x[(size_t)b * T * 2 + i];
    sK0[tid] = kern[tid];
    sK1[tid] = kern[G4 + tid];
    sb[tid] = bias[tid];
    if (tid < H) { sh[tid] = h0[b * H + tid]; sVs[tid] = V[tid]; }
    float creg = (tid < H) ? c0[b * H + tid] : 0.0f;
    if (tid == 0) { sptr[0] = 1.0f; sptr[1] = 1.0f; }
    __syncthreads();
    if (tid < H) ((float*)sv4)[tid] = -2.0f * sVs[tid];
    if (tid == 0) {
        float sv = 0.0f;
        for (int h = 0; h < H; h++) sv += sVs[h];
        s_sumV = sv;
    }
    __syncthreads();
    float sumV = s_sumV;

    const float4* wp4 = (const float4*)g_P + (size_t)b * 32 * T + tid;
    bool is_g = ((tid >> 7) == 2);  // warp-uniform: g-gate quarter

    for (int s = 0; s < T; s++) {
        // ---- A: partial z, thread (p = h-quarter, q = gate quad): 32 x LDG.128 ----
        {
            int p = tid >> 7, q = tid & 127;
            const float4* rk = (const float4*)reck + q;
            float4 a = make_float4(0.f, 0.f, 0.f, 0.f);
            int hb = p * 32;
#pragma unroll 8
            for (int h = 0; h < 32; h++) {
                float hv = sh[hb + h];
                float4 r4 = __ldg(rk + (size_t)(hb + h) * 128);
                a.x = fmaf(hv, r4.x, a.x);
                a.y = fmaf(hv, r4.y, a.y);
                a.z = fmaf(hv, r4.z, a.z);
                a.w = fmaf(hv, r4.w, a.w);
            }
            spart4[tid] = a;
        }
        __syncthreads();

        // ---- B1: z-reduce + activation, one gate per thread (512-way) ----
        {
            const float* sp = (const float*)spart4;
            float p0 = sptr[0], p1 = sptr[1];
            float z = fmaf(p1, sK1[tid], fmaf(p0, sK0[tid], sb[tid]))
                    + ((sp[tid] + sp[512 + tid]) + (sp[1024 + tid] + sp[1536 + tid]));
            float t = tanh_safe(is_g ? z : 0.5f * z);
            sact[tid] = is_g ? t : fmaf(0.5f, t, 0.5f);
        }
        __syncthreads();

        // ---- B2: cell update (threads 0..127) ----
        if (tid < H) {
            float c2 = sact[tid + H] * creg + sact[tid] * sact[tid + 2 * H];
            creg = c2;
            sh[tid] = sact[tid + 3 * H] * tanh_safe(c2);
        }
        __syncthreads();

        // ---- C: partial u, thread (p2 = h-16th, g = out quad): 8 x LDG.128 ----
        {
            int p2 = tid >> 5, g = tid & 31;
            const float4* w2 = (const float4*)W2 + g;
            float4 a = make_float4(0.f, 0.f, 0.f, 0.f);
            int hb = p2 * 8;
#pragma unroll
            for (int h = 0; h < 8; h++) {
                float hv = sh[hb + h];
                float4 w = __ldg(w2 + (size_t)(hb + h) * 32);
                a.x = fmaf(hv, w.x, a.x);
                a.y = fmaf(hv, w.y, a.y);
                a.z = fmaf(hv, w.z, a.z);
                a.w = fmaf(hv, w.w, a.w);
            }
            spart4[tid] = a;
        }
        __syncthreads();

        // ---- C-reduce: Eu[j] = 2^{clamp(u*2log2e)} (threads 0..127) ----
        if (tid < H) {
            const float* sp = (const float*)spart4;
            float u = 0.0f;
#pragma unroll
            for (int p2 = 0; p2 < 16; p2++) u += sp[p2 * 128 + tid];
            ((float*)sEu4)[tid] = ex2f(fminf(u * K2LOG2E, 15.0f));
        }
        __syncthreads();

        // ---- D: score = sumV + sum quads [4-way combined rcp], d = P*Eu + 1 ----
        float acc0 = 0.0f, acc1 = 0.0f;
#pragma unroll 8
        for (int qd = 0; qd < 32; qd++) {
            float4 P = __ldcg(wp4 + (size_t)qd * T);
            float4 Eu = sEu4[qd];
            float4 Vv = sv4[qd];
            float d0 = fmaf(P.x, Eu.x, 1.0f);
            float d1 = fmaf(P.y, Eu.y, 1.0f);
            float d2 = fmaf(P.z, Eu.z, 1.0f);
            float d3 = fmaf(P.w, Eu.w, 1.0f);
            float d01 = d0 * d1, d23 = d2 * d3;
            float n01 = Vv.x * d1;
            n01 = fmaf(Vv.y, d0, n01);
            float n23 = Vv.z * d3;
            n23 = fmaf(Vv.w, d2, n23);
            float num = n01 * d23;
            num = fmaf(n23, d01, num);
            float r = rcpf(d01 * d23);
            if (qd & 1) acc1 = fmaf(num, r, acc1);
            else        acc0 = fmaf(num, r, acc0);
        }
        float score = sumV + (acc0 + acc1);
        __stcs(out + ((size_t)b * T + s) * T + tid, score);

        // ---- argmax (tie -> lowest index) + pointer select ----
        float best = score;
        int bidx = tid;
#pragma unroll
        for (int o = 16; o > 0; o >>= 1) {
            float ov = __shfl_xor_sync(0xffffffffu, best, o);
            int oi = __shfl_xor_sync(0xffffffffu, bidx, o);
            if (ov > best || (ov == best && oi < bidx)) { best = ov; bidx = oi; }
        }
        if (lane == 0) { rv[wid] = best; ri[wid] = bidx; }
        __syncthreads();
        if (wid == 0) {
            float bb = (lane < 16) ? rv[lane] : rv[0];
            int bi = (lane < 16) ? ri[lane] : ri[0];
#pragma unroll
            for (int o = 8; o > 0; o >>= 1) {
                float ov = __shfl_xor_sync(0xffffffffu, bb, o);
                int oi = __shfl_xor_sync(0xffffffffu, bi, o);
                if (ov > bb || (ov == bb && oi < bi)) { bb = ov; bi = oi; }
            }
            if (lane == 0) {
                sptr[0] = sx[bi * 2];
                sptr[1] = sx[bi * 2 + 1];
            }
        }
        __syncthreads();
    }
}

// ---------------- launch: 2 graph nodes ----------------
extern "C" void kernel_launch(void* const* d_in, const int* in_sizes, int n_in,
                              void* d_out, int out_size) {
    const float* x = (const float*)d_in[0];
    const float* enc = (const float*)d_in[1];
    const float* h0 = (const float*)d_in[2];
    const float* c0 = (const float*)d_in[3];
    const float* kern = (const float*)d_in[4];
    const float* reck = (const float*)d_in[5];
    const float* bias = (const float*)d_in[6];
    const float* W1 = (const float*)d_in[7];
    const float* W2 = (const float*)d_in[8];
    const float* V = (const float*)d_in[9];
    float* out = (float*)d_out;

    const int smem_w1e = (128 * 128 + 64 * 129) * 4;  // 98560 B
    cudaFuncSetAttribute(w1e_kernel, cudaFuncAttributeMaxDynamicSharedMemorySize, smem_w1e);
    w1e_kernel<<<B * 8, 256, smem_w1e>>>(enc, W1);
    decoder_kernel<<<B, 512>>>(x, h0, c0, kern, reck, bias, W2, V, out);
}